// round 10
// baseline (speedup 1.0000x reference)
#include <cuda_runtime.h>
#include <math.h>

#define TT 8
#define NI 20000
#define NK 50000
#define FF 128
#define HH 256
#define OO 128
#define EE 500000
#define MAXS 512
#define NKW ((NK + 31) / 32)        // 1563 bitmap words
#define SCAN_BLK 123                 // ceil((EE/4) / (4*256))
#define SCAN_STRIDE (SCAN_BLK * 256)

// ---------------- scratch (device globals; no allocation allowed) ----------------
__device__ int      g_item_flag[TT][NK];   // -1 empty, -2 marked, >=0 slot
__device__ int      g_item_mult[TT][NK];   // edge multiplicity (src,target) in e2
__device__ unsigned g_bitmap[TT][NKW];     // 1 bit per slotted item
__device__ int      g_item_id[TT][MAXS];
__device__ int      g_item_cnt[TT][MAXS];  // e1 in-degree of needed item
__device__ float    g_item_acc[TT][MAXS][FF];
__device__ float    g_hitem[TT][MAXS][HH];
__device__ int      g_num_items[TT];
__device__ float    g_accx[TT][FF];        // sum of x_item over target's e2 edges
__device__ int      g_edge_cnt[TT];
__device__ float    g_seq[TT][OO];
__device__ float    g_gi[TT][3 * HH];
__device__ float    g_hbuf[2][HH];
__device__ float    g_rnn[TT][HH];

// ---------------- init / reset ----------------
__global__ void k_init() {
    int idx = blockIdx.x * blockDim.x + threadIdx.x;
    if (idx < TT * NK) {
        ((int*)g_item_flag)[idx] = -1;
        ((int*)g_item_mult)[idx] = 0;
    }
    if (idx < TT * MAXS * FF) ((float*)g_item_acc)[idx] = 0.0f;
    if (idx < TT * MAXS)      ((int*)g_item_cnt)[idx] = 0;
    if (idx < TT * FF)        ((float*)g_accx)[idx] = 0.0f;
    if (idx < TT * NKW)       ((unsigned*)g_bitmap)[idx] = 0u;
    if (idx < TT) { g_edge_cnt[idx] = 0; g_num_items[idx] = 0; }
    if (idx < 2 * HH) ((float*)g_hbuf)[idx] = 0.0f;
}

// ---------------- pass A: scan e2, 4x int4 front-batched ----------------
__device__ __forceinline__ void e2_hit(int t, int e, const int* __restrict__ s,
                                       const float* __restrict__ x_item) {
    int src = s[e];
    atomicAdd(&g_edge_cnt[t], 1);
    atomicAdd(&g_item_mult[t][src], 1);
    int old = atomicExch(&g_item_flag[t][src], -2);
    if (old == -1) {
        int sl = atomicAdd(&g_num_items[t], 1);
        if (sl < MAXS) g_item_id[t][sl] = src;
    }
    const float* xr = x_item + ((size_t)t * NK + src) * FF;
    #pragma unroll 4
    for (int f = 0; f < FF; f++) atomicAdd(&g_accx[t][f], xr[f]);
}

__global__ void k_scan_e2(const int* __restrict__ e2s, const int* __restrict__ e2d,
                          const float* __restrict__ x_item, const int* __restrict__ tgtp) {
    int t = blockIdx.y;
    int tgt = *tgtp;
    const int4* d4 = (const int4*)(e2d + (size_t)t * EE);
    const int* s = e2s + (size_t)t * EE;
    int tidx = blockIdx.x * blockDim.x + threadIdx.x;
    int4 v[4]; int ok[4];
    #pragma unroll
    for (int k = 0; k < 4; k++) {
        int idx = tidx + k * SCAN_STRIDE;
        ok[k] = idx < EE / 4;
        v[k] = ok[k] ? __ldg(d4 + idx) : make_int4(-1, -1, -1, -1);
    }
    #pragma unroll
    for (int k = 0; k < 4; k++) {
        if (!ok[k]) continue;
        int e = 4 * (tidx + k * SCAN_STRIDE);
        if (v[k].x == tgt) e2_hit(t, e + 0, s, x_item);
        if (v[k].y == tgt) e2_hit(t, e + 1, s, x_item);
        if (v[k].z == tgt) e2_hit(t, e + 2, s, x_item);
        if (v[k].w == tgt) e2_hit(t, e + 3, s, x_item);
    }
}

// ---------------- pass A2: assign slot ids + build bitmap ----------------
__global__ void k_assign() {
    int t = blockIdx.x;
    if (threadIdx.x == 0 && g_num_items[t] > MAXS) g_num_items[t] = MAXS;
    __syncthreads();
    int n = g_num_items[t];
    for (int k = threadIdx.x; k < n; k += blockDim.x) {
        int id = g_item_id[t][k];
        g_item_flag[t][id] = k;
        atomicOr(&g_bitmap[t][id >> 5], 1u << (id & 31));
    }
}

// ---------------- pass B: scan e1, smem-bitmap probes + 4x int4 ----------------
__device__ __forceinline__ void e1_hit(int t, int sl, int e, const int* __restrict__ s,
                                       const float* __restrict__ x_inf) {
    atomicAdd(&g_item_cnt[t][sl], 1);
    int src = s[e];
    const float* xr = x_inf + ((size_t)t * NI + src) * FF;
    #pragma unroll 4
    for (int f = 0; f < FF; f++) atomicAdd(&g_item_acc[t][sl][f], xr[f]);
}

__global__ void k_scan_e1(const int* __restrict__ e1s, const int* __restrict__ e1d,
                          const float* __restrict__ x_inf) {
    int t = blockIdx.y;
    __shared__ unsigned bm[NKW];
    for (int w = threadIdx.x; w < NKW; w += blockDim.x) bm[w] = g_bitmap[t][w];
    __syncthreads();
    const int4* d4 = (const int4*)(e1d + (size_t)t * EE);
    const int* s = e1s + (size_t)t * EE;
    const int* flag = g_item_flag[t];
    int tidx = blockIdx.x * blockDim.x + threadIdx.x;
    int4 v[4]; int ok[4];
    #pragma unroll
    for (int k = 0; k < 4; k++) {
        int idx = tidx + k * SCAN_STRIDE;
        ok[k] = idx < EE / 4;
        v[k] = ok[k] ? __ldg(d4 + idx) : make_int4(0, 0, 0, 0);
    }
    #pragma unroll
    for (int k = 0; k < 4; k++) {
        if (!ok[k]) continue;
        int e = 4 * (tidx + k * SCAN_STRIDE);
        int d0 = v[k].x, d1 = v[k].y, d2 = v[k].z, d3 = v[k].w;
        if ((bm[d0 >> 5] >> (d0 & 31)) & 1u) { int f = flag[d0]; if (f >= 0) e1_hit(t, f, e + 0, s, x_inf); }
        if ((bm[d1 >> 5] >> (d1 & 31)) & 1u) { int f = flag[d1]; if (f >= 0) e1_hit(t, f, e + 1, s, x_inf); }
        if ((bm[d2 >> 5] >> (d2 & 31)) & 1u) { int f = flag[d2]; if (f >= 0) e1_hit(t, f, e + 2, s, x_inf); }
        if ((bm[d3 >> 5] >> (d3 & 31)) & 1u) { int f = flag[d3]; if (f >= 0) e1_hit(t, f, e + 3, s, x_inf); }
    }
}

__device__ __forceinline__ float warp_sum(float v) {
    #pragma unroll
    for (int off = 16; off > 0; off >>= 1) v += __shfl_down_sync(0xffffffffu, v, off);
    return v;
}

// ---------------- pass C: h_item, COALESCED warp-per-row (R8-proven) ----------------
__global__ void k_hitem(const float* __restrict__ x_item,
                        const float* __restrict__ W1a_l, const float* __restrict__ b1a_l,
                        const float* __restrict__ W1a_r) {
    int t = blockIdx.y;
    int tid = threadIdx.x;
    int wid = tid >> 5, lane = tid & 31;
    __shared__ float4 mean4[FF / 4], xrow4[FF / 4];
    for (int sl = blockIdx.x; sl < g_num_items[t]; sl += gridDim.x) {
        int id = g_item_id[t][sl];
        float c = fmaxf((float)g_item_cnt[t][sl], 1.0f);
        if (tid < FF) {
            ((float*)mean4)[tid] = g_item_acc[t][sl][tid] / c;
            ((float*)xrow4)[tid] = x_item[((size_t)t * NK + id) * FF + tid];
        }
        __syncthreads();
        float4 m = mean4[lane], x = xrow4[lane];
        for (int h = wid; h < HH; h += 8) {
            float4 wl = ((const float4*)(W1a_l + (size_t)h * FF))[lane];
            float4 wr = ((const float4*)(W1a_r + (size_t)h * FF))[lane];
            float a = wl.x * m.x + wl.y * m.y + wl.z * m.z + wl.w * m.w
                    + wr.x * x.x + wr.y * x.y + wr.z * x.z + wr.w * x.w;
            a = warp_sum(a);
            if (lane == 0) g_hitem[t][sl][h] = fmaxf(a + b1a_l[h], 0.0f);
        }
        __syncthreads();
    }
}

// ---------------- pass D: h_inf[target] + o_inf[target], COALESCED (R8-proven) ----------------
__global__ void k_oinf(const float* __restrict__ x_inf,
                       const float* __restrict__ W1b_l, const float* __restrict__ b1b_l,
                       const float* __restrict__ W1b_r,
                       const float* __restrict__ W2b_l, const float* __restrict__ b2b_l,
                       const float* __restrict__ W2b_r,
                       const int* __restrict__ tgtp) {
    int t = blockIdx.x;
    int tid = threadIdx.x;
    int wid = tid >> 5, lane = tid & 31;
    int tgt = *tgtp;
    __shared__ float4 meanx4[FF / 4], xt4[FF / 4];
    __shared__ float4 hinf4[HH / 4], meanh4[HH / 4];
    __shared__ float multw[MAXS];
    float ec = fmaxf((float)g_edge_cnt[t], 1.0f);
    int n = g_num_items[t];
    if (n > MAXS) n = MAXS;
    if (tid < FF) {
        ((float*)meanx4)[tid] = g_accx[t][tid] / ec;
        ((float*)xt4)[tid]    = x_inf[((size_t)t * NI + tgt) * FF + tid];
    }
    for (int k = tid; k < n; k += blockDim.x)
        multw[k] = (float)g_item_mult[t][g_item_id[t][k]];
    __syncthreads();

    {
        float mh = 0.0f;
        for (int k = 0; k < n; k++) mh += multw[k] * g_hitem[t][k][tid];
        ((float*)meanh4)[tid] = mh / ec;
    }
    {
        float4 m = meanx4[lane], x = xt4[lane];
        for (int h = wid; h < HH; h += 8) {
            float4 wl = ((const float4*)(W1b_l + (size_t)h * FF))[lane];
            float4 wr = ((const float4*)(W1b_r + (size_t)h * FF))[lane];
            float a = wl.x * m.x + wl.y * m.y + wl.z * m.z + wl.w * m.w
                    + wr.x * x.x + wr.y * x.y + wr.z * x.z + wr.w * x.w;
            a = warp_sum(a);
            if (lane == 0) ((float*)hinf4)[h] = fmaxf(a + b1b_l[h], 0.0f);
        }
    }
    __syncthreads();

    {
        float4 m0 = meanh4[lane], m1 = meanh4[lane + 32];
        float4 h0 = hinf4[lane],  h1 = hinf4[lane + 32];
        for (int o = wid; o < OO; o += 8) {
            const float4* wl = (const float4*)(W2b_l + (size_t)o * HH);
            const float4* wr = (const float4*)(W2b_r + (size_t)o * HH);
            float4 a0 = wl[lane], a1 = wl[lane + 32];
            float4 b0 = wr[lane], b1 = wr[lane + 32];
            float v = a0.x * m0.x + a0.y * m0.y + a0.z * m0.z + a0.w * m0.w
                    + a1.x * m1.x + a1.y * m1.y + a1.z * m1.z + a1.w * m1.w
                    + b0.x * h0.x + b0.y * h0.y + b0.z * h0.z + b0.w * h0.w
                    + b1.x * h1.x + b1.y * h1.y + b1.z * h1.z + b1.w * h1.w;
            v = warp_sum(v);
            if (lane == 0) g_seq[t][o] = v + b2b_l[o];
        }
    }
}

// ---------------- GRU input gates, COALESCED warp-per-row (R8-proven) ----------------
__global__ void k_gi(const float* __restrict__ W_ih, const float* __restrict__ b_ih) {
    int t = blockIdx.y;
    int tid = threadIdx.x;
    int wid = tid >> 5, lane = tid & 31;
    __shared__ float4 xs4[OO / 4];
    if (tid < OO) ((float*)xs4)[tid] = g_seq[t][tid];
    __syncthreads();
    float4 x = xs4[lane];
    int gw = blockIdx.x * 8 + wid;           // 0..95 global warps
    for (int row = gw; row < 3 * HH; row += 96) {
        float4 w = ((const float4*)(W_ih + (size_t)row * OO))[lane];
        float v = w.x * x.x + w.y * x.y + w.z * x.z + w.w * x.w;
        v = warp_sum(v);
        if (lane == 0) g_gi[t][row] = v + b_ih[row];
    }
}

// ---------------- one GRU step: warp per h-row (R1-proven, untouched) ----------------
__global__ void k_gru(int t, const float* __restrict__ W_hh, const float* __restrict__ b_hh) {
    const float* hprev = g_hbuf[t & 1];
    float* hnext = g_hbuf[(t + 1) & 1];
    int gwarp = (blockIdx.x * blockDim.x + threadIdx.x) >> 5;
    int lane = threadIdx.x & 31;
    if (gwarp >= HH) return;
    int w = gwarp;
    float sr = 0.0f, sz = 0.0f, sn = 0.0f;
    const float* wr = W_hh + (size_t)w * HH;
    const float* wz = W_hh + (size_t)(HH + w) * HH;
    const float* wn = W_hh + (size_t)(2 * HH + w) * HH;
    #pragma unroll
    for (int j = 0; j < HH / 32; j++) {
        int k = lane + 32 * j;
        float hv = hprev[k];
        sr += wr[k] * hv;
        sz += wz[k] * hv;
        sn += wn[k] * hv;
    }
    #pragma unroll
    for (int off = 16; off > 0; off >>= 1) {
        sr += __shfl_down_sync(0xffffffffu, sr, off);
        sz += __shfl_down_sync(0xffffffffu, sz, off);
        sn += __shfl_down_sync(0xffffffffu, sn, off);
    }
    if (lane == 0) {
        float gh_r = sr + b_hh[w];
        float gh_z = sz + b_hh[HH + w];
        float gh_n = sn + b_hh[2 * HH + w];
        float gi_r = g_gi[t][w];
        float gi_z = g_gi[t][HH + w];
        float gi_n = g_gi[t][2 * HH + w];
        float r = 1.0f / (1.0f + expf(-(gi_r + gh_r)));
        float z = 1.0f / (1.0f + expf(-(gi_z + gh_z)));
        float nn = tanhf(gi_n + r * gh_n);
        float hn = (1.0f - z) * nn + z * hprev[w];
        hnext[w] = hn;
        g_rnn[t][w] = hn;
    }
}

// ---------------- attention + prediction head (R1-proven, untouched) ----------------
__global__ void k_head(const float* __restrict__ W_att, const float* __restrict__ b_att,
                       const float* __restrict__ W_p1, const float* __restrict__ b_p1,
                       const float* __restrict__ W_p2, const float* __restrict__ b_p2,
                       float* __restrict__ out) {
    __shared__ float att[TT], ctx[HH], red[HH];
    int tid = threadIdx.x;
    if (tid < TT) {
        float lg = b_att[0];
        for (int h = 0; h < HH; h++) lg += g_rnn[tid][h] * W_att[h];
        att[tid] = lg;
    }
    __syncthreads();
    if (tid == 0) {
        float m = att[0];
        for (int t = 1; t < TT; t++) m = fmaxf(m, att[t]);
        float s = 0.0f;
        for (int t = 0; t < TT; t++) { att[t] = expf(att[t] - m); s += att[t]; }
        for (int t = 0; t < TT; t++) att[t] /= s;
    }
    __syncthreads();
    {
        float c = 0.0f;
        #pragma unroll
        for (int t = 0; t < TT; t++) c += att[t] * g_rnn[t][tid];
        ctx[tid] = c;
    }
    __syncthreads();
    if (tid < HH / 2) {
        float v = b_p1[tid];
        const float* w = W_p1 + (size_t)tid * HH;
        #pragma unroll 8
        for (int h = 0; h < HH; h++) v += w[h] * ctx[h];
        v = fmaxf(v, 0.0f);
        red[tid] = v * W_p2[tid];
    }
    __syncthreads();
    if (tid == 0) {
        float s = b_p2[0];
        for (int j = 0; j < HH / 2; j++) s += red[j];
        out[0] = s;
    }
}

extern "C" void kernel_launch(void* const* d_in, const int* in_sizes, int n_in,
                              void* d_out, int out_size) {
    const float* x_inf  = (const float*)d_in[0];
    const float* x_item = (const float*)d_in[1];
    const int*   e1s    = (const int*)d_in[2];
    const int*   e1d    = (const int*)d_in[3];
    const int*   e2s    = (const int*)d_in[4];
    const int*   e2d    = (const int*)d_in[5];
    const int*   tgt    = (const int*)d_in[6];
    const float* W1a_l  = (const float*)d_in[7];
    const float* b1a_l  = (const float*)d_in[8];
    const float* W1a_r  = (const float*)d_in[9];
    const float* W1b_l  = (const float*)d_in[10];
    const float* b1b_l  = (const float*)d_in[11];
    const float* W1b_r  = (const float*)d_in[12];
    // d_in[13..15]: W2a_* (dead code in reference — o_item unused)
    const float* W2b_l  = (const float*)d_in[16];
    const float* b2b_l  = (const float*)d_in[17];
    const float* W2b_r  = (const float*)d_in[18];
    const float* W_ih   = (const float*)d_in[19];
    const float* W_hh   = (const float*)d_in[20];
    const float* b_ih   = (const float*)d_in[21];
    const float* b_hh   = (const float*)d_in[22];
    const float* W_att  = (const float*)d_in[23];
    const float* b_att  = (const float*)d_in[24];
    const float* W_p1   = (const float*)d_in[25];
    const float* b_p1   = (const float*)d_in[26];
    const float* W_p2   = (const float*)d_in[27];
    const float* b_p2   = (const float*)d_in[28];
    float* out = (float*)d_out;

    k_init<<<2048, 256>>>();
    dim3 gscan(SCAN_BLK, TT);
    k_scan_e2<<<gscan, 256>>>(e2s, e2d, x_item, tgt);
    k_assign<<<TT, 256>>>();
    k_scan_e1<<<gscan, 256>>>(e1s, e1d, x_inf);
    k_hitem<<<dim3(64, TT), 256>>>(x_item, W1a_l, b1a_l, W1a_r);
    k_oinf<<<TT, 256>>>(x_inf, W1b_l, b1b_l, W1b_r, W2b_l, b2b_l, W2b_r, tgt);
    k_gi<<<dim3(12, TT), 256>>>(W_ih, b_ih);
    for (int t = 0; t < TT; t++)
        k_gru<<<32, 256>>>(t, W_hh, b_hh);
    k_head<<<1, 256>>>(W_att, b_att, W_p1, b_p1, W_p2, b_p2, out);
}

// round 11
// speedup vs baseline: 1.1650x; 1.1650x over previous
#include <cuda_runtime.h>
#include <math.h>

#define TT 8
#define NI 20000
#define NK 50000
#define FF 128
#define HH 256
#define OO 128
#define EE 500000
#define MAXS 512
#define NKW ((NK + 31) / 32)        // 1563 bitmap words
#define SCAN_BLK 123                 // ceil((EE/4) / (4*256))
#define SCAN_STRIDE (SCAN_BLK * 256)
#define FULLW 0xffffffffu

// ---------------- scratch (device globals; no allocation allowed) ----------------
__device__ int      g_item_flag[TT][NK];   // -1 empty, -2 marked, >=0 slot
__device__ int      g_item_mult[TT][NK];   // edge multiplicity (src,target) in e2
__device__ unsigned g_bitmap[TT][NKW];     // 1 bit per slotted item
__device__ int      g_item_id[TT][MAXS];
__device__ int      g_item_cnt[TT][MAXS];  // e1 in-degree of needed item
__device__ float    g_item_acc[TT][MAXS][FF];
__device__ float    g_hitem[TT][MAXS][HH];
__device__ int      g_num_items[TT];
__device__ float    g_accx[TT][FF];        // sum of x_item over target's e2 edges
__device__ int      g_edge_cnt[TT];
__device__ float    g_seq[TT][OO];
__device__ float    g_gi[TT][3 * HH];
__device__ float    g_hbuf[2][HH];
__device__ float    g_rnn[TT][HH];

// ---------------- init / reset ----------------
__global__ void k_init() {
    int idx = blockIdx.x * blockDim.x + threadIdx.x;
    if (idx < TT * NK) {
        ((int*)g_item_flag)[idx] = -1;
        ((int*)g_item_mult)[idx] = 0;
    }
    if (idx < TT * MAXS * FF) ((float*)g_item_acc)[idx] = 0.0f;
    if (idx < TT * MAXS)      ((int*)g_item_cnt)[idx] = 0;
    if (idx < TT * FF)        ((float*)g_accx)[idx] = 0.0f;
    if (idx < TT * NKW)       ((unsigned*)g_bitmap)[idx] = 0u;
    if (idx < TT) { g_edge_cnt[idx] = 0; g_num_items[idx] = 0; }
    if (idx < 2 * HH) ((float*)g_hbuf)[idx] = 0.0f;
}

// ---------------- pass A: scan e2, warp-cooperative hit path ----------------
__global__ void k_scan_e2(const int* __restrict__ e2s, const int* __restrict__ e2d,
                          const float* __restrict__ x_item, const int* __restrict__ tgtp) {
    int t = blockIdx.y;
    int tgt = *tgtp;
    const int4* d4 = (const int4*)(e2d + (size_t)t * EE);
    const int* s = e2s + (size_t)t * EE;
    int lane = threadIdx.x & 31;
    int tidx = blockIdx.x * blockDim.x + threadIdx.x;
    int4 v[4]; int ok[4];
    #pragma unroll
    for (int k = 0; k < 4; k++) {
        int idx = tidx + k * SCAN_STRIDE;
        ok[k] = idx < EE / 4;
        v[k] = ok[k] ? __ldg(d4 + idx) : make_int4(-1, -1, -1, -1);
    }
    #pragma unroll
    for (int k = 0; k < 4; k++) {
        int e = 4 * (tidx + k * SCAN_STRIDE);
        #pragma unroll
        for (int j = 0; j < 4; j++) {
            int dv = (j == 0) ? v[k].x : (j == 1) ? v[k].y : (j == 2) ? v[k].z : v[k].w;
            bool hit = ok[k] && (dv == tgt);
            unsigned m = __ballot_sync(FULLW, hit);
            while (m) {
                int ldr = __ffs(m) - 1;
                m &= m - 1;
                int eb = __shfl_sync(FULLW, e + j, ldr);
                int src = 0;
                if (lane == ldr) src = s[eb];
                src = __shfl_sync(FULLW, src, ldr);
                if (lane == 0) {
                    atomicAdd(&g_edge_cnt[t], 1);
                    atomicAdd(&g_item_mult[t][src], 1);
                    int old = atomicExch(&g_item_flag[t][src], -2);
                    if (old == -1) {
                        int sl = atomicAdd(&g_num_items[t], 1);
                        if (sl < MAXS) g_item_id[t][sl] = src;
                    }
                }
                float4 xv = ((const float4*)(x_item + ((size_t)t * NK + src) * FF))[lane];
                atomicAdd(&g_accx[t][4 * lane + 0], xv.x);
                atomicAdd(&g_accx[t][4 * lane + 1], xv.y);
                atomicAdd(&g_accx[t][4 * lane + 2], xv.z);
                atomicAdd(&g_accx[t][4 * lane + 3], xv.w);
            }
        }
    }
}

// ---------------- pass A2: assign slot ids + build bitmap ----------------
__global__ void k_assign() {
    int t = blockIdx.x;
    if (threadIdx.x == 0 && g_num_items[t] > MAXS) g_num_items[t] = MAXS;
    __syncthreads();
    int n = g_num_items[t];
    for (int k = threadIdx.x; k < n; k += blockDim.x) {
        int id = g_item_id[t][k];
        g_item_flag[t][id] = k;
        atomicOr(&g_bitmap[t][id >> 5], 1u << (id & 31));
    }
}

// ---------------- pass B: scan e1, bitmap + warp-cooperative hit path ----------------
__global__ void k_scan_e1(const int* __restrict__ e1s, const int* __restrict__ e1d,
                          const float* __restrict__ x_inf) {
    int t = blockIdx.y;
    __shared__ unsigned bm[NKW];
    for (int w = threadIdx.x; w < NKW; w += blockDim.x) bm[w] = g_bitmap[t][w];
    __syncthreads();
    const int4* d4 = (const int4*)(e1d + (size_t)t * EE);
    const int* s = e1s + (size_t)t * EE;
    const int* flag = g_item_flag[t];
    int lane = threadIdx.x & 31;
    int tidx = blockIdx.x * blockDim.x + threadIdx.x;
    int4 v[4]; int ok[4];
    #pragma unroll
    for (int k = 0; k < 4; k++) {
        int idx = tidx + k * SCAN_STRIDE;
        ok[k] = idx < EE / 4;
        v[k] = ok[k] ? __ldg(d4 + idx) : make_int4(0, 0, 0, 0);
    }
    #pragma unroll
    for (int k = 0; k < 4; k++) {
        int e = 4 * (tidx + k * SCAN_STRIDE);
        #pragma unroll
        for (int j = 0; j < 4; j++) {
            int dv = (j == 0) ? v[k].x : (j == 1) ? v[k].y : (j == 2) ? v[k].z : v[k].w;
            int sl = -1;
            if (ok[k] && ((bm[dv >> 5] >> (dv & 31)) & 1u)) sl = flag[dv];
            bool hit = sl >= 0;
            unsigned m = __ballot_sync(FULLW, hit);
            while (m) {
                int ldr = __ffs(m) - 1;
                m &= m - 1;
                int slb = __shfl_sync(FULLW, sl, ldr);
                int eb = __shfl_sync(FULLW, e + j, ldr);
                int src = 0;
                if (lane == ldr) src = s[eb];
                src = __shfl_sync(FULLW, src, ldr);
                if (lane == 0) atomicAdd(&g_item_cnt[t][slb], 1);
                float4 xv = ((const float4*)(x_inf + ((size_t)t * NI + src) * FF))[lane];
                atomicAdd(&g_item_acc[t][slb][4 * lane + 0], xv.x);
                atomicAdd(&g_item_acc[t][slb][4 * lane + 1], xv.y);
                atomicAdd(&g_item_acc[t][slb][4 * lane + 2], xv.z);
                atomicAdd(&g_item_acc[t][slb][4 * lane + 3], xv.w);
            }
        }
    }
}

__device__ __forceinline__ float warp_sum(float v) {
    #pragma unroll
    for (int off = 16; off > 0; off >>= 1) v += __shfl_down_sync(0xffffffffu, v, off);
    return v;
}

// ---------------- pass C: h_item, COALESCED warp-per-row (R8-proven) ----------------
__global__ void k_hitem(const float* __restrict__ x_item,
                        const float* __restrict__ W1a_l, const float* __restrict__ b1a_l,
                        const float* __restrict__ W1a_r) {
    int t = blockIdx.y;
    int tid = threadIdx.x;
    int wid = tid >> 5, lane = tid & 31;
    __shared__ float4 mean4[FF / 4], xrow4[FF / 4];
    for (int sl = blockIdx.x; sl < g_num_items[t]; sl += gridDim.x) {
        int id = g_item_id[t][sl];
        float c = fmaxf((float)g_item_cnt[t][sl], 1.0f);
        if (tid < FF) {
            ((float*)mean4)[tid] = g_item_acc[t][sl][tid] / c;
            ((float*)xrow4)[tid] = x_item[((size_t)t * NK + id) * FF + tid];
        }
        __syncthreads();
        float4 m = mean4[lane], x = xrow4[lane];
        for (int h = wid; h < HH; h += 8) {
            float4 wl = ((const float4*)(W1a_l + (size_t)h * FF))[lane];
            float4 wr = ((const float4*)(W1a_r + (size_t)h * FF))[lane];
            float a = wl.x * m.x + wl.y * m.y + wl.z * m.z + wl.w * m.w
                    + wr.x * x.x + wr.y * x.y + wr.z * x.z + wr.w * x.w;
            a = warp_sum(a);
            if (lane == 0) g_hitem[t][sl][h] = fmaxf(a + b1a_l[h], 0.0f);
        }
        __syncthreads();
    }
}

// ---------------- pass D: h_inf[target] + o_inf[target], COALESCED (R8-proven) ----------------
__global__ void k_oinf(const float* __restrict__ x_inf,
                       const float* __restrict__ W1b_l, const float* __restrict__ b1b_l,
                       const float* __restrict__ W1b_r,
                       const float* __restrict__ W2b_l, const float* __restrict__ b2b_l,
                       const float* __restrict__ W2b_r,
                       const int* __restrict__ tgtp) {
    int t = blockIdx.x;
    int tid = threadIdx.x;
    int wid = tid >> 5, lane = tid & 31;
    int tgt = *tgtp;
    __shared__ float4 meanx4[FF / 4], xt4[FF / 4];
    __shared__ float4 hinf4[HH / 4], meanh4[HH / 4];
    __shared__ float multw[MAXS];
    float ec = fmaxf((float)g_edge_cnt[t], 1.0f);
    int n = g_num_items[t];
    if (n > MAXS) n = MAXS;
    if (tid < FF) {
        ((float*)meanx4)[tid] = g_accx[t][tid] / ec;
        ((float*)xt4)[tid]    = x_inf[((size_t)t * NI + tgt) * FF + tid];
    }
    for (int k = tid; k < n; k += blockDim.x)
        multw[k] = (float)g_item_mult[t][g_item_id[t][k]];
    __syncthreads();

    {
        float mh = 0.0f;
        for (int k = 0; k < n; k++) mh += multw[k] * g_hitem[t][k][tid];
        ((float*)meanh4)[tid] = mh / ec;
    }
    {
        float4 m = meanx4[lane], x = xt4[lane];
        for (int h = wid; h < HH; h += 8) {
            float4 wl = ((const float4*)(W1b_l + (size_t)h * FF))[lane];
            float4 wr = ((const float4*)(W1b_r + (size_t)h * FF))[lane];
            float a = wl.x * m.x + wl.y * m.y + wl.z * m.z + wl.w * m.w
                    + wr.x * x.x + wr.y * x.y + wr.z * x.z + wr.w * x.w;
            a = warp_sum(a);
            if (lane == 0) ((float*)hinf4)[h] = fmaxf(a + b1b_l[h], 0.0f);
        }
    }
    __syncthreads();

    {
        float4 m0 = meanh4[lane], m1 = meanh4[lane + 32];
        float4 h0 = hinf4[lane],  h1 = hinf4[lane + 32];
        for (int o = wid; o < OO; o += 8) {
            const float4* wl = (const float4*)(W2b_l + (size_t)o * HH);
            const float4* wr = (const float4*)(W2b_r + (size_t)o * HH);
            float4 a0 = wl[lane], a1 = wl[lane + 32];
            float4 b0 = wr[lane], b1 = wr[lane + 32];
            float v = a0.x * m0.x + a0.y * m0.y + a0.z * m0.z + a0.w * m0.w
                    + a1.x * m1.x + a1.y * m1.y + a1.z * m1.z + a1.w * m1.w
                    + b0.x * h0.x + b0.y * h0.y + b0.z * h0.z + b0.w * h0.w
                    + b1.x * h1.x + b1.y * h1.y + b1.z * h1.z + b1.w * h1.w;
            v = warp_sum(v);
            if (lane == 0) g_seq[t][o] = v + b2b_l[o];
        }
    }
}

// ---------------- GRU input gates, COALESCED warp-per-row (R8-proven) ----------------
__global__ void k_gi(const float* __restrict__ W_ih, const float* __restrict__ b_ih) {
    int t = blockIdx.y;
    int tid = threadIdx.x;
    int wid = tid >> 5, lane = tid & 31;
    __shared__ float4 xs4[OO / 4];
    if (tid < OO) ((float*)xs4)[tid] = g_seq[t][tid];
    __syncthreads();
    float4 x = xs4[lane];
    int gw = blockIdx.x * 8 + wid;           // 0..95 global warps
    for (int row = gw; row < 3 * HH; row += 96) {
        float4 w = ((const float4*)(W_ih + (size_t)row * OO))[lane];
        float v = w.x * x.x + w.y * x.y + w.z * x.z + w.w * x.w;
        v = warp_sum(v);
        if (lane == 0) g_gi[t][row] = v + b_ih[row];
    }
}

// ---------------- one GRU step: warp per h-row (R1-proven, untouched) ----------------
__global__ void k_gru(int t, const float* __restrict__ W_hh, const float* __restrict__ b_hh) {
    const float* hprev = g_hbuf[t & 1];
    float* hnext = g_hbuf[(t + 1) & 1];
    int gwarp = (blockIdx.x * blockDim.x + threadIdx.x) >> 5;
    int lane = threadIdx.x & 31;
    if (gwarp >= HH) return;
    int w = gwarp;
    float sr = 0.0f, sz = 0.0f, sn = 0.0f;
    const float* wr = W_hh + (size_t)w * HH;
    const float* wz = W_hh + (size_t)(HH + w) * HH;
    const float* wn = W_hh + (size_t)(2 * HH + w) * HH;
    #pragma unroll
    for (int j = 0; j < HH / 32; j++) {
        int k = lane + 32 * j;
        float hv = hprev[k];
        sr += wr[k] * hv;
        sz += wz[k] * hv;
        sn += wn[k] * hv;
    }
    #pragma unroll
    for (int off = 16; off > 0; off >>= 1) {
        sr += __shfl_down_sync(0xffffffffu, sr, off);
        sz += __shfl_down_sync(0xffffffffu, sz, off);
        sn += __shfl_down_sync(0xffffffffu, sn, off);
    }
    if (lane == 0) {
        float gh_r = sr + b_hh[w];
        float gh_z = sz + b_hh[HH + w];
        float gh_n = sn + b_hh[2 * HH + w];
        float gi_r = g_gi[t][w];
        float gi_z = g_gi[t][HH + w];
        float gi_n = g_gi[t][2 * HH + w];
        float r = 1.0f / (1.0f + expf(-(gi_r + gh_r)));
        float z = 1.0f / (1.0f + expf(-(gi_z + gh_z)));
        float nn = tanhf(gi_n + r * gh_n);
        float hn = (1.0f - z) * nn + z * hprev[w];
        hnext[w] = hn;
        g_rnn[t][w] = hn;
    }
}

// ---------------- attention + prediction head (R1-proven, untouched) ----------------
__global__ void k_head(const float* __restrict__ W_att, const float* __restrict__ b_att,
                       const float* __restrict__ W_p1, const float* __restrict__ b_p1,
                       const float* __restrict__ W_p2, const float* __restrict__ b_p2,
                       float* __restrict__ out) {
    __shared__ float att[TT], ctx[HH], red[HH];
    int tid = threadIdx.x;
    if (tid < TT) {
        float lg = b_att[0];
        for (int h = 0; h < HH; h++) lg += g_rnn[tid][h] * W_att[h];
        att[tid] = lg;
    }
    __syncthreads();
    if (tid == 0) {
        float m = att[0];
        for (int t = 1; t < TT; t++) m = fmaxf(m, att[t]);
        float s = 0.0f;
        for (int t = 0; t < TT; t++) { att[t] = expf(att[t] - m); s += att[t]; }
        for (int t = 0; t < TT; t++) att[t] /= s;
    }
    __syncthreads();
    {
        float c = 0.0f;
        #pragma unroll
        for (int t = 0; t < TT; t++) c += att[t] * g_rnn[t][tid];
        ctx[tid] = c;
    }
    __syncthreads();
    if (tid < HH / 2) {
        float v = b_p1[tid];
        const float* w = W_p1 + (size_t)tid * HH;
        #pragma unroll 8
        for (int h = 0; h < HH; h++) v += w[h] * ctx[h];
        v = fmaxf(v, 0.0f);
        red[tid] = v * W_p2[tid];
    }
    __syncthreads();
    if (tid == 0) {
        float s = b_p2[0];
        for (int j = 0; j < HH / 2; j++) s += red[j];
        out[0] = s;
    }
}

extern "C" void kernel_launch(void* const* d_in, const int* in_sizes, int n_in,
                              void* d_out, int out_size) {
    const float* x_inf  = (const float*)d_in[0];
    const float* x_item = (const float*)d_in[1];
    const int*   e1s    = (const int*)d_in[2];
    const int*   e1d    = (const int*)d_in[3];
    const int*   e2s    = (const int*)d_in[4];
    const int*   e2d    = (const int*)d_in[5];
    const int*   tgt    = (const int*)d_in[6];
    const float* W1a_l  = (const float*)d_in[7];
    const float* b1a_l  = (const float*)d_in[8];
    const float* W1a_r  = (const float*)d_in[9];
    const float* W1b_l  = (const float*)d_in[10];
    const float* b1b_l  = (const float*)d_in[11];
    const float* W1b_r  = (const float*)d_in[12];
    // d_in[13..15]: W2a_* (dead code in reference — o_item unused)
    const float* W2b_l  = (const float*)d_in[16];
    const float* b2b_l  = (const float*)d_in[17];
    const float* W2b_r  = (const float*)d_in[18];
    const float* W_ih   = (const float*)d_in[19];
    const float* W_hh   = (const float*)d_in[20];
    const float* b_ih   = (const float*)d_in[21];
    const float* b_hh   = (const float*)d_in[22];
    const float* W_att  = (const float*)d_in[23];
    const float* b_att  = (const float*)d_in[24];
    const float* W_p1   = (const float*)d_in[25];
    const float* b_p1   = (const float*)d_in[26];
    const float* W_p2   = (const float*)d_in[27];
    const float* b_p2   = (const float*)d_in[28];
    float* out = (float*)d_out;

    k_init<<<2048, 256>>>();
    dim3 gscan(SCAN_BLK, TT);
    k_scan_e2<<<gscan, 256>>>(e2s, e2d, x_item, tgt);
    k_assign<<<TT, 256>>>();
    k_scan_e1<<<gscan, 256>>>(e1s, e1d, x_inf);
    k_hitem<<<dim3(64, TT), 256>>>(x_item, W1a_l, b1a_l, W1a_r);
    k_oinf<<<TT, 256>>>(x_inf, W1b_l, b1b_l, W1b_r, W2b_l, b2b_l, W2b_r, tgt);
    k_gi<<<dim3(12, TT), 256>>>(W_ih, b_ih);
    for (int t = 0; t < TT; t++)
        k_gru<<<32, 256>>>(t, W_hh, b_hh);
    k_head<<<1, 256>>>(W_att, b_att, W_p1, b_p1, W_p2, b_p2, out);
}